// round 17
// baseline (speedup 1.0000x reference)
#include <cuda_runtime.h>

#define BATCH  16
#define H      1024
#define HW     (H*H)
#define NSTRIP 11
#define NBANDS 11
#define BANDH  94                      // 11*94 = 1034 >= 1024
#define TASKS  (BATCH*NSTRIP*NBANDS)   // 1936
#define WPB    14
#define NT     448
#define NCTA   ((TASKS+WPB-1)/WPB)     // 139
#define WARPF4 1024                    // ring: 32 slots x 32 f4 = 16 KB/warp

__device__ float        g_accum[BATCH * 5];
__device__ unsigned int g_count;

__device__ __forceinline__ float4 f4z() { return make_float4(0.f, 0.f, 0.f, 0.f); }
__device__ __forceinline__ void addf4(float4& a, const float4 b) { a.x+=b.x; a.y+=b.y; a.z+=b.z; a.w+=b.w; }

__device__ __forceinline__ void epi(float x, float m, float S3, float S15, float S31,
                                    float& a0, float& a1, float& a2, float& a3, float& a4)
{
    float w = 1.f + 5.f * ( fabsf(S3  * (1.f / 9.f)   - m)
                          + fabsf(S15 * (1.f / 225.f) - m)
                          + fabsf(S31 * (1.f / 961.f) - m) );
    float e   = __expf(-fabsf(x));
    float l   = __logf(1.f + e);
    float bce = fmaxf(x, 0.f) - x * m + l;
    float inv = __fdividef(1.f, 1.f + e);
    float sg  = (x >= 0.f) ? inv : e * inv;
    a0 += w;
    a1 += w * bce;
    a2 += sg * m * w;
    a3 += (sg + m) * w;
    a4 += fabsf(sg - m);
}

__global__ __launch_bounds__(NT, 1) void adaptive_loss_main(
    const float* __restrict__ pred, const float* __restrict__ mask, float* __restrict__ out)
{
    extern __shared__ float4 sm4[];
    unsigned int* sflag = (unsigned int*)(sm4 + WPB * WARPF4);
    const int tid  = threadIdx.x;
    const int lane = tid & 31;
    const int warp = tid >> 5;
    const int task = blockIdx.x * WPB + warp;

    float a0 = 0.f, a1 = 0.f, a2 = 0.f, a3 = 0.f, a4 = 0.f;
    int b = 0;

    if (task < TASKS) {
        b = task / (NSTRIP * NBANDS);
        const int rem  = task % (NSTRIP * NBANDS);
        const int s    = rem / NBANDS;
        const int band = rem % NBANDS;
        const int y0   = band * BANDH;
        const int rows = (H - y0 < BANDH) ? (H - y0) : BANDH;

        const float4* mb4 = (const float4*)(mask + (size_t)b * HW);
        const float4* pb4 = (const float4*)(pred + (size_t)b * HW);

        const int  w     = 24 * s - 4 + lane;     // global f4 word
        const bool ok    = ((unsigned)w < 256u);
        const bool dataT = (lane >= 4) && (lane <= 27) && ((24 * s + lane - 4) < 256);

        float4* rg = sm4 + warp * WARPF4;         // per-warp, per-lane ring: slot*32 + lane

        float4 U31 = f4z(), U15 = f4z(), U3 = f4z();

        // ---------- priming: rows y0-16 .. y0+14 ----------
        float4 mCur;
        {
            int r = y0 - 16;
            mCur = (r >= 0 && ok) ? mb4[(size_t)r * 256 + w] : f4z();
        }
        float4 mP = f4z(), mPm1 = f4z(), mPm2 = f4z();
        #pragma unroll 1
        for (int j = 0; j < 31; ++j) {
            const int r = y0 - 16 + j, rn = r + 1;
            float4 mN = (rn >= 0 && rn < H && ok) ? mb4[(size_t)rn * 256 + w] : f4z();

            float4 v = mCur; v.y += v.x; v.z += v.y; v.w += v.z;
            float tot = v.w;
            #pragma unroll
            for (int d = 1; d < 32; d <<= 1) {
                float u = __shfl_up_sync(0xffffffffu, tot, d);
                if (lane >= d) tot += u;
            }
            const float ex = tot - v.w;
            float4 P = make_float4(v.x + ex, v.y + ex, v.z + ex, v.w + ex);
            rg[((r + 512) & 31) * 32 + lane] = P;

            addf4(U31, P);
            if (j >= 8  && j <= 22) addf4(U15, P);
            if (j >= 14 && j <= 16) addf4(U3,  P);
            if (j == 14) mPm2 = P;                 // P(y0-2)
            if (j == 15) mPm1 = P;                 // P(y0-1)
            if (j == 16) mP   = P;                 // P(y0)

            mCur = mN;
        }
        // mCur = raw mask row y0+15; U centered at y0-1

        float4 pCur = dataT ? pb4[(size_t)y0 * 256 + w] : f4z();

        // ---------- main: consume row y in the same iteration ----------
        #pragma unroll 1
        for (int i = 0; i < rows; ++i) {
            const int y  = y0 + i;
            const int rn = y + 16;
            float4 mN = (rn < H && ok) ? mb4[(size_t)rn * 256 + w] : f4z();
            float4 pN = (dataT && (y + 1 < H)) ? pb4[(size_t)(y + 1) * 256 + w] : f4z();

            // warp-local scan of mask row y+15
            float4 v = mCur; v.y += v.x; v.z += v.y; v.w += v.z;
            float tot = v.w;
            #pragma unroll
            for (int d = 1; d < 32; d <<= 1) {
                float u = __shfl_up_sync(0xffffffffu, tot, d);
                if (lane >= d) tot += u;
            }
            const float ex = tot - v.w;
            float4 P = make_float4(v.x + ex, v.y + ex, v.z + ex, v.w + ex);
            rg[((y + 15) & 31) * 32 + lane] = P;

            // own-lane ring taps (the ONLY smem reads)
            float4 t16 = rg[((y - 16 + 512) & 31) * 32 + lane];
            float4 t7  = rg[((y + 7)        & 31) * 32 + lane];
            float4 t8  = rg[((y - 8 + 512)  & 31) * 32 + lane];
            float4 t1  = rg[((y + 1)        & 31) * 32 + lane];

            U31.x += P.x - t16.x; U31.y += P.y - t16.y; U31.z += P.z - t16.z; U31.w += P.w - t16.w;
            U15.x += t7.x - t8.x; U15.y += t7.y - t8.y; U15.z += t7.z - t8.z; U15.w += t7.w - t8.w;
            U3.x  += t1.x - mPm2.x; U3.y += t1.y - mPm2.y; U3.z += t1.z - mPm2.z; U3.w += t1.w - mPm2.w;

            // cross-lane values via register shuffles (uniform execution)
            float a31w = __shfl_down_sync(0xffffffffu, U31.w, 3);
            float b31x = __shfl_down_sync(0xffffffffu, U31.x, 4);
            float b31y = __shfl_down_sync(0xffffffffu, U31.y, 4);
            float b31z = __shfl_down_sync(0xffffffffu, U31.z, 4);
            float c31x = __shfl_up_sync(0xffffffffu, U31.x, 4);
            float c31y = __shfl_up_sync(0xffffffffu, U31.y, 4);
            float c31z = __shfl_up_sync(0xffffffffu, U31.z, 4);
            float c31w = __shfl_up_sync(0xffffffffu, U31.w, 4);
            float a15w = __shfl_down_sync(0xffffffffu, U15.w, 1);
            float b15x = __shfl_down_sync(0xffffffffu, U15.x, 2);
            float b15y = __shfl_down_sync(0xffffffffu, U15.y, 2);
            float b15z = __shfl_down_sync(0xffffffffu, U15.z, 2);
            float c15x = __shfl_up_sync(0xffffffffu, U15.x, 2);
            float c15y = __shfl_up_sync(0xffffffffu, U15.y, 2);
            float c15z = __shfl_up_sync(0xffffffffu, U15.z, 2);
            float c15w = __shfl_up_sync(0xffffffffu, U15.w, 2);
            float uz = __shfl_up_sync(0xffffffffu, U3.z, 1);      // U3(4L-2)
            float uw = __shfl_up_sync(0xffffffffu, U3.w, 1);      // U3(4L-1)
            float dx = __shfl_down_sync(0xffffffffu, U3.x, 1);    // U3(4L+4)
            float mlw = __shfl_up_sync(0xffffffffu, mP.w, 1);     // P(y)[4L-1]

            if (dataT) {
                float m0 = mP.x - mlw,  m1 = mP.y - mP.x;
                float m2 = mP.z - mP.y, m3 = mP.w - mP.z;

                epi(pCur.x, m0, U3.y - uz,   a15w - c15x, a31w - c31x, a0, a1, a2, a3, a4);
                epi(pCur.y, m1, U3.z - uw,   b15x - c15y, b31x - c31y, a0, a1, a2, a3, a4);
                epi(pCur.z, m2, U3.w - U3.x, b15y - c15z, b31y - c31z, a0, a1, a2, a3, a4);
                epi(pCur.w, m3, dx - U3.y,   b15z - c15w, b31z - c31w, a0, a1, a2, a3, a4);
            }

            mPm2 = mPm1; mPm1 = mP; mP = t1;       // rotate P(y-2),P(y-1),P(y) pipeline
            mCur = mN; pCur = pN;
        }

        // warp reduce + per-warp atomics
        #pragma unroll
        for (int d = 16; d > 0; d >>= 1) {
            a0 += __shfl_down_sync(0xffffffffu, a0, d);
            a1 += __shfl_down_sync(0xffffffffu, a1, d);
            a2 += __shfl_down_sync(0xffffffffu, a2, d);
            a3 += __shfl_down_sync(0xffffffffu, a3, d);
            a4 += __shfl_down_sync(0xffffffffu, a4, d);
        }
        if (lane == 0) {
            atomicAdd(&g_accum[b * 5 + 0], a0);
            atomicAdd(&g_accum[b * 5 + 1], a1);
            atomicAdd(&g_accum[b * 5 + 2], a2);
            atomicAdd(&g_accum[b * 5 + 3], a3);
            atomicAdd(&g_accum[b * 5 + 4], a4);
        }
    }

    // ---- last-block finalize ----
    __threadfence();
    __syncthreads();
    if (tid == 0) {
        unsigned int cdone = atomicAdd(&g_count, 1u);
        *sflag = (cdone == (unsigned int)(gridDim.x - 1)) ? 1u : 0u;
    }
    __syncthreads();
    if (*sflag && tid == 0) {
        float vals[BATCH * 5];
        #pragma unroll 1
        for (int i = 0; i < BATCH * 5; ++i) vals[i] = atomicAdd(&g_accum[i], 0.f);
        float mae_total = 0.f;
        for (int bb = 0; bb < BATCH; ++bb) mae_total += vals[bb * 5 + 4];
        const float mae = mae_total / (float)((long long)BATCH * HW);
        float acc = 0.f;
        for (int bb = 0; bb < BATCH; ++bb) {
            float ws = vals[bb * 5 + 0];
            float wb = vals[bb * 5 + 1];
            float it = vals[bb * 5 + 2];
            float un = vals[bb * 5 + 3];
            float wbce = wb / ws;
            float wiou = 1.f - (it + 1.f) / (un - it + 1.f);
            float wmae = mae * ws / (ws - (float)HW);
            acc += 0.7f * (wbce + wiou + wmae);
        }
        out[0] = acc / (float)BATCH;
        #pragma unroll 1
        for (int i = 0; i < BATCH * 5; ++i) g_accum[i] = 0.f;
        __threadfence();
        atomicExch(&g_count, 0u);
    }
}

extern "C" void kernel_launch(void* const* d_in, const int* in_sizes, int n_in,
                              void* d_out, int out_size) {
    const float* pred = (const float*)d_in[0];
    const float* mask = (const float*)d_in[1];
    float* out = (float*)d_out;

    const int smem_bytes = WPB * WARPF4 * 16 + 16;   // 229,392 B
    cudaFuncSetAttribute(adaptive_loss_main,
                         cudaFuncAttributeMaxDynamicSharedMemorySize, smem_bytes);
    adaptive_loss_main<<<NCTA, NT, smem_bytes>>>(pred, mask, out);
}